// round 8
// baseline (speedup 1.0000x reference)
#include <cuda_runtime.h>
#include <cstdint>

// Problem shapes
#define BATCH 8
#define NC    28
#define HH    256
#define WCC   310
#define WPP   256

static constexpr int HWC = HH * WCC;                 // 79360 (%4==0)
static constexpr int HWP = HH * WPP;                 // 65536
static constexpr int NPIX_C = BATCH * HWC;           // 634880
static constexpr int NPIX_P = BATCH * HWP;           // 524288
static constexpr int XC_ELEMS = BATCH * NC * HWC;    // 17,776,640

// float4 path: 4 pixels/thread, 128 threads/block -> 512 pixels/block.
//   xc: 634880/512 = 1240 = 8*155,  xp: 524288/512 = 1024 = 8*128
// Interleave: 8 groups x (155 xc + 128 xp); group g covers EXACTLY batch g
// in both domains, so xp's shifted z reads hit the z lines (8.9 MB/group)
// the xc blocks just pulled into L2.
static constexpr int XC_BLK_PER_GRP = 155;
static constexpr int GRP_BLKS = 283;

// Non-CSE-able vector loads (force a reload of phi in the output loop so the
// compiler does NOT keep 28 float4 phi values live in registers).
__device__ __forceinline__ float4 ld_f4(const float* p) {
    float4 v;
    asm volatile("ld.global.v4.f32 {%0,%1,%2,%3}, [%4];"
                 : "=f"(v.x), "=f"(v.y), "=f"(v.z), "=f"(v.w)
                 : "l"(p));
    return v;
}

__global__ void __launch_bounds__(128, 3)
dp_fused_kernel(const float* __restrict__ z,
                const float* __restrict__ yc,
                const float* __restrict__ phi_c,
                const float* __restrict__ yp,
                const float* __restrict__ phi_p,
                const float* __restrict__ xc_k_1,
                const float* __restrict__ xp_k_1,
                const float* __restrict__ mu,
                const float* __restrict__ mu_c,
                const float* __restrict__ mu_p,
                float* __restrict__ out)
{
    const int g = blockIdx.x / GRP_BLKS;
    const int j = blockIdx.x - g * GRP_BLKS;
    const float mu_ = mu[0];

    // out[c] = m[c] + t*phi[c],  m[c] = wA*z[c] + wz*x[c],
    // t = (y - sum_c m[c]*phi[c]) / (mu + mu_x + sum_c phi[c]^2)
    if (j < XC_BLK_PER_GRP) {
        // ---------------- xc update (coded domain, W=310) ----------------
        const int pix = ((g * XC_BLK_PER_GRP + j) * 128 + threadIdx.x) * 4; // %4==0
        const float muc = mu_c[0];
        const float inv = 1.f / (mu_ + muc);
        const float wA  = muc * inv;
        const float wz  = mu_ * inv;
        const int b    = pix / HWC;
        const int rem  = pix - b * HWC;          // %4==0
        const int base = b * (NC * HWC) + rem;   // 16B aligned

        float4 mr[NC];
        float4 s  = make_float4(0.f, 0.f, 0.f, 0.f);
        float4 am = make_float4(0.f, 0.f, 0.f, 0.f);
        #pragma unroll
        for (int c = 0; c < NC; ++c) {
            const int o = base + c * HWC;
            const float4 zv = *(const float4*)(z      + o);
            const float4 pv = *(const float4*)(phi_c  + o);
            const float4 xv = *(const float4*)(xp_k_1 + o);
            float4 m;
            m.x = fmaf(wz, xv.x, wA * zv.x);
            m.y = fmaf(wz, xv.y, wA * zv.y);
            m.z = fmaf(wz, xv.z, wA * zv.z);
            m.w = fmaf(wz, xv.w, wA * zv.w);
            mr[c] = m;
            s.x = fmaf(pv.x, pv.x, s.x);  s.y = fmaf(pv.y, pv.y, s.y);
            s.z = fmaf(pv.z, pv.z, s.z);  s.w = fmaf(pv.w, pv.w, s.w);
            am.x = fmaf(m.x, pv.x, am.x); am.y = fmaf(m.y, pv.y, am.y);
            am.z = fmaf(m.z, pv.z, am.z); am.w = fmaf(m.w, pv.w, am.w);
        }
        if (s.x == 0.f) s.x = 1.f;
        if (s.y == 0.f) s.y = 1.f;
        if (s.z == 0.f) s.z = 1.f;
        if (s.w == 0.f) s.w = 1.f;
        const float4 y4 = *(const float4*)(yc + pix);
        const float d = mu_ + muc;
        float4 t;
        t.x = (y4.x - am.x) / (d + s.x);
        t.y = (y4.y - am.y) / (d + s.y);
        t.z = (y4.z - am.z) / (d + s.z);
        t.w = (y4.w - am.w) / (d + s.w);

        #pragma unroll
        for (int c = 0; c < NC; ++c) {
            const int o = base + c * HWC;
            const float4 pv = ld_f4(phi_c + o);   // L1/L2 hit (loaded above)
            float4 o4;
            o4.x = fmaf(t.x, pv.x, mr[c].x);
            o4.y = fmaf(t.y, pv.y, mr[c].y);
            o4.z = fmaf(t.z, pv.z, mr[c].z);
            o4.w = fmaf(t.w, pv.w, mr[c].w);
            *(float4*)(out + o) = o4;
        }
    } else {
        // ---------------- xp update (PAN domain, W=256) ----------------
        const int jb  = g * (GRP_BLKS - XC_BLK_PER_GRP) + (j - XC_BLK_PER_GRP);
        const int pix = (jb * 128 + threadIdx.x) * 4;   // %4==0
        const float mup = mu_p[0];
        const float inv = 1.f / (mu_ + mup);
        const float wA  = mup * inv;
        const float wz  = mu_ * inv;
        const int b   = pix / HWP;
        const int rem = pix - b * HWP;           // %4==0
        const int h   = rem >> 8;                // WP = 256
        const int w   = rem & 255;               // %4==0
        const int basep = b * (NC * HWP) + rem;                 // 16B aligned
        const int basec = b * (NC * HWC) + h * WCC + w;         // even (maybe %4==2)

        float4 mr[NC];
        float4 s  = make_float4(0.f, 0.f, 0.f, 0.f);
        float4 am = make_float4(0.f, 0.f, 0.f, 0.f);
        #pragma unroll
        for (int c = 0; c < NC; ++c) {
            // shift_back: z[b,c,h,w+2c .. w+3+2c]; w+3+2c <= 309, no wrap.
            // Offset only 8B-aligned (h*310 odd-even) -> two float2 loads.
            const int oz = basec + c * HWC + 2 * c;
            const float2 zlo = *(const float2*)(z + oz);
            const float2 zhi = *(const float2*)(z + oz + 2);
            const int  o  = basep + c * HWP;
            const float4 pv = *(const float4*)(phi_p  + o);
            const float4 xv = *(const float4*)(xc_k_1 + o);
            float4 m;
            m.x = fmaf(wz, xv.x, wA * zlo.x);
            m.y = fmaf(wz, xv.y, wA * zlo.y);
            m.z = fmaf(wz, xv.z, wA * zhi.x);
            m.w = fmaf(wz, xv.w, wA * zhi.y);
            mr[c] = m;
            s.x = fmaf(pv.x, pv.x, s.x);  s.y = fmaf(pv.y, pv.y, s.y);
            s.z = fmaf(pv.z, pv.z, s.z);  s.w = fmaf(pv.w, pv.w, s.w);
            am.x = fmaf(m.x, pv.x, am.x); am.y = fmaf(m.y, pv.y, am.y);
            am.z = fmaf(m.z, pv.z, am.z); am.w = fmaf(m.w, pv.w, am.w);
        }
        if (s.x == 0.f) s.x = 1.f;
        if (s.y == 0.f) s.y = 1.f;
        if (s.z == 0.f) s.z = 1.f;
        if (s.w == 0.f) s.w = 1.f;
        const float4 y4 = *(const float4*)(yp + pix);
        const float d = mu_ + mup;
        float4 t;
        t.x = (y4.x - am.x) / (d + s.x);
        t.y = (y4.y - am.y) / (d + s.y);
        t.z = (y4.z - am.z) / (d + s.z);
        t.w = (y4.w - am.w) / (d + s.w);

        float* __restrict__ outp = out + XC_ELEMS;
        #pragma unroll
        for (int c = 0; c < NC; ++c) {
            const int o = basep + c * HWP;
            const float4 pv = ld_f4(phi_p + o);   // L1/L2 hit
            float4 o4;
            o4.x = fmaf(t.x, pv.x, mr[c].x);
            o4.y = fmaf(t.y, pv.y, mr[c].y);
            o4.z = fmaf(t.z, pv.z, mr[c].z);
            o4.w = fmaf(t.w, pv.w, mr[c].w);
            *(float4*)(outp + o) = o4;
        }
    }
}

extern "C" void kernel_launch(void* const* d_in, const int* in_sizes, int n_in,
                              void* d_out, int out_size)
{
    const float* z      = (const float*)d_in[0];
    const float* yc     = (const float*)d_in[1];
    const float* phi_c  = (const float*)d_in[2];
    const float* yp     = (const float*)d_in[3];
    const float* phi_p  = (const float*)d_in[4];
    const float* xc_k_1 = (const float*)d_in[5];
    const float* xp_k_1 = (const float*)d_in[6];
    const float* mu     = (const float*)d_in[7];
    const float* mu_c   = (const float*)d_in[8];
    const float* mu_p   = (const float*)d_in[9];
    float* out = (float*)d_out;

    const int blocks = (NPIX_C + NPIX_P) / 512;   // 2264 = 8 * 283
    dp_fused_kernel<<<blocks, 128>>>(z, yc, phi_c, yp, phi_p,
                                     xc_k_1, xp_k_1, mu, mu_c, mu_p, out);
}

// round 9
// speedup vs baseline: 1.3464x; 1.3464x over previous
#include <cuda_runtime.h>

// Problem shapes (compile-time constants)
#define BATCH 8
#define NC    28
#define HH    256
#define WCC   310
#define WPP   256

static constexpr int HWC = HH * WCC;                 // 79360 (even)
static constexpr int HWP = HH * WPP;                 // 65536
static constexpr int NPIX_C = BATCH * HWC;           // 634880
static constexpr int NPIX_P = BATCH * HWP;           // 524288
static constexpr int XC_ELEMS = BATCH * NC * HWC;    // 17,776,640

// float2 path: each thread handles 2 adjacent pixels -> 128-thread blocks
// cover 256 pixels:
//   xc: 634880/256 = 2480 = 16*155,  xp: 524288/256 = 2048 = 16*128
// Interleave: 16 groups x (155 xc + 128 xp); each group covers half a batch
// image in both domains so xp's shifted z reads hit L2.
static constexpr int XC_BLK_PER_GRP = 155;
static constexpr int GRP_BLKS = 283;

__global__ void __launch_bounds__(128, 3)
dp_fused_kernel(const float* __restrict__ z,
                const float* __restrict__ yc,
                const float* __restrict__ phi_c,
                const float* __restrict__ yp,
                const float* __restrict__ phi_p,
                const float* __restrict__ xc_k_1,
                const float* __restrict__ xp_k_1,
                const float* __restrict__ mu,
                const float* __restrict__ mu_c,
                const float* __restrict__ mu_p,
                float* __restrict__ out)
{
    const int g = blockIdx.x / GRP_BLKS;
    const int j = blockIdx.x - g * GRP_BLKS;
    const float mu_ = mu[0];

    // out[c] = m[c] + t*phi[c],  m[c] = wA*z[c] + wz*x[c],
    // t = (y - sum_c m[c]*phi[c]) / (mu + mu_x + sum_c phi[c]^2)
    if (j < XC_BLK_PER_GRP) {
        // ---------------- xc update (coded domain, W=310) ----------------
        const int pix = ((g * XC_BLK_PER_GRP + j) * 128 + threadIdx.x) * 2; // even
        const float muc = mu_c[0];
        const float inv = 1.f / (mu_ + muc);
        const float wA  = muc * inv;
        const float wz  = mu_ * inv;
        const int b    = pix / HWC;
        const int rem  = pix - b * HWC;          // even
        const int base = b * (NC * HWC) + rem;   // 8B aligned

        // Hoisted: overlap y's DRAM latency with the channel-load burst.
        const float2 y2 = *(const float2*)(yc + pix);

        float2 mr[NC], pr[NC];
        float2 s  = make_float2(0.f, 0.f);
        float2 am = make_float2(0.f, 0.f);
        #pragma unroll
        for (int c = 0; c < NC; ++c) {
            const int o = base + c * HWC;
            const float2 zv = *(const float2*)(z      + o);
            const float2 pv = *(const float2*)(phi_c  + o);
            const float2 xv = *(const float2*)(xp_k_1 + o);
            float2 m;
            m.x = fmaf(wz, xv.x, wA * zv.x);
            m.y = fmaf(wz, xv.y, wA * zv.y);
            mr[c] = m; pr[c] = pv;
            s.x  = fmaf(pv.x, pv.x, s.x);
            s.y  = fmaf(pv.y, pv.y, s.y);
            am.x = fmaf(m.x, pv.x, am.x);
            am.y = fmaf(m.y, pv.y, am.y);
        }
        if (s.x == 0.f) s.x = 1.f;
        if (s.y == 0.f) s.y = 1.f;
        float2 t;
        t.x = (y2.x - am.x) / (mu_ + muc + s.x);
        t.y = (y2.y - am.y) / (mu_ + muc + s.y);

        #pragma unroll
        for (int c = 0; c < NC; ++c) {
            float2 o2;
            o2.x = fmaf(t.x, pr[c].x, mr[c].x);
            o2.y = fmaf(t.y, pr[c].y, mr[c].y);
            *(float2*)(out + base + c * HWC) = o2;
        }
    } else {
        // ---------------- xp update (PAN domain, W=256) ----------------
        const int jb  = g * (GRP_BLKS - XC_BLK_PER_GRP) + (j - XC_BLK_PER_GRP);
        const int pix = (jb * 128 + threadIdx.x) * 2;   // even
        const float mup = mu_p[0];
        const float inv = 1.f / (mu_ + mup);
        const float wA  = mup * inv;
        const float wz  = mu_ * inv;
        const int b   = pix / HWP;
        const int rem = pix - b * HWP;           // even
        const int h   = rem >> 8;                // WP = 256
        const int w   = rem & 255;               // even
        const int basep = b * (NC * HWP) + rem;                 // phi_p / xc_k_1 / out
        const int basec = b * (NC * HWC) + h * WCC + w;         // z (shifted), even

        const float2 y2 = *(const float2*)(yp + pix);  // hoisted

        float2 mr[NC], pr[NC];
        float2 s  = make_float2(0.f, 0.f);
        float2 am = make_float2(0.f, 0.f);
        #pragma unroll
        for (int c = 0; c < NC; ++c) {
            // shift_back: z[b,c,h,w+2c] and z[b,c,h,w+1+2c]; w+1+2c <= 309, no wrap.
            const float2 zv = *(const float2*)(z + basec + c * HWC + 2 * c);
            const int  o  = basep + c * HWP;
            const float2 pv = *(const float2*)(phi_p  + o);
            const float2 xv = *(const float2*)(xc_k_1 + o);
            float2 m;
            m.x = fmaf(wz, xv.x, wA * zv.x);
            m.y = fmaf(wz, xv.y, wA * zv.y);
            mr[c] = m; pr[c] = pv;
            s.x  = fmaf(pv.x, pv.x, s.x);
            s.y  = fmaf(pv.y, pv.y, s.y);
            am.x = fmaf(m.x, pv.x, am.x);
            am.y = fmaf(m.y, pv.y, am.y);
        }
        if (s.x == 0.f) s.x = 1.f;
        if (s.y == 0.f) s.y = 1.f;
        float2 t;
        t.x = (y2.x - am.x) / (mu_ + mup + s.x);
        t.y = (y2.y - am.y) / (mu_ + mup + s.y);

        float* __restrict__ outp = out + XC_ELEMS;
        #pragma unroll
        for (int c = 0; c < NC; ++c) {
            float2 o2;
            o2.x = fmaf(t.x, pr[c].x, mr[c].x);
            o2.y = fmaf(t.y, pr[c].y, mr[c].y);
            *(float2*)(outp + basep + c * HWP) = o2;
        }
    }
}

extern "C" void kernel_launch(void* const* d_in, const int* in_sizes, int n_in,
                              void* d_out, int out_size)
{
    const float* z      = (const float*)d_in[0];
    const float* yc     = (const float*)d_in[1];
    const float* phi_c  = (const float*)d_in[2];
    const float* yp     = (const float*)d_in[3];
    const float* phi_p  = (const float*)d_in[4];
    const float* xc_k_1 = (const float*)d_in[5];
    const float* xp_k_1 = (const float*)d_in[6];
    const float* mu     = (const float*)d_in[7];
    const float* mu_c   = (const float*)d_in[8];
    const float* mu_p   = (const float*)d_in[9];
    float* out = (float*)d_out;

    const int blocks = (NPIX_C + NPIX_P) / 256;   // 4528 = 16 * 283
    dp_fused_kernel<<<blocks, 128>>>(z, yc, phi_c, yp, phi_p,
                                     xc_k_1, xp_k_1, mu, mu_c, mu_p, out);
}